// round 7
// baseline (speedup 1.0000x reference)
#include <cuda_runtime.h>
#include <cuda_fp16.h>
#include <cstdint>

#define NODES_TOTAL 100000
#define NNODES      20000
#define TN          50
#define INF         256
#define HIDF        256
#define OUTF        256
#define CATF        512

// Scratch (static __device__ arrays: allocation-free per harness rules)
__device__ __align__(16) __half g_qh[(size_t)NODES_TOTAL * HIDF];  // 51.2 MB (L2-resident)
__device__ __align__(16) __half g_cat[(size_t)NNODES * CATF];      // 20.5 MB

// ---------------------------------------------------------------------------
// helpers
// ---------------------------------------------------------------------------
__device__ __forceinline__ void mma_f16_f32acc(float c[4], const uint32_t a[4],
                                               uint32_t b0, uint32_t b1) {
    asm volatile("mma.sync.aligned.m16n8k16.row.col.f32.f16.f16.f32 "
                 "{%0,%1,%2,%3}, {%4,%5,%6,%7}, {%8,%9}, {%0,%1,%2,%3};"
                 : "+f"(c[0]), "+f"(c[1]), "+f"(c[2]), "+f"(c[3])
                 : "r"(a[0]), "r"(a[1]), "r"(a[2]), "r"(a[3]), "r"(b0), "r"(b1));
}

__device__ __forceinline__ void mma_f16_f16acc(uint32_t c[2], const uint32_t a[4],
                                               uint32_t b0, uint32_t b1) {
    asm volatile("mma.sync.aligned.m16n8k16.row.col.f16.f16.f16.f16 "
                 "{%0,%1}, {%2,%3,%4,%5}, {%6,%7}, {%0,%1};"
                 : "+r"(c[0]), "+r"(c[1])
                 : "r"(a[0]), "r"(a[1]), "r"(a[2]), "r"(a[3]), "r"(b0), "r"(b1));
}

__device__ __forceinline__ void ldmatrix_x4(uint32_t r[4], uint32_t saddr) {
    asm volatile("ldmatrix.sync.aligned.m8n8.x4.shared.b16 {%0,%1,%2,%3}, [%4];"
                 : "=r"(r[0]), "=r"(r[1]), "=r"(r[2]), "=r"(r[3]) : "r"(saddr));
}

__device__ __forceinline__ uint32_t pack_h2(float x, float y) {
    __half2 h = __float22half2_rn(make_float2(x, y));
    return *(uint32_t*)&h;
}

// ===========================================================================
// GEMM-A: QH[m, n0..n0+127] = relu( h[m,:] @ Qw[n,:] + Qb[n] ), fp16 out.
// A fp32 [M,256], B fp32 [256,256]. CTA tile 128x128, 8 warps (64x32 each).
// B staged to smem ONCE (full K, stride 264 halves: 528B row; 528 mod 128 =
// 16 -> ldmatrix 8-row groups hit distinct 16B banks). A double-buffered per
// 32-wide K chunk with register prefetch. fp16 accumulators (2x legacy-HMMA
// rate hypothesis); error attenuated ~7x by downstream 50-neighbor mean.
// One __syncthreads per chunk (store targets the buffer whose readers
// finished before the previous end-of-chunk sync).
// ===========================================================================
#define SROWA 40    // A smem row stride (halves)
#define SROWB 264   // B smem row stride (halves), full K=256 + 8 pad

#define GEMM_A_SMEM (2 * 128 * SROWA * 2 + 128 * SROWB * 2)   // 88064 B

__global__ __launch_bounds__(256, 2) void gemm_a_kernel(
    const float* __restrict__ A, const float* __restrict__ B,
    const float* __restrict__ bias, __half* __restrict__ C, int M)
{
    extern __shared__ __half dsm[];
    __half* sA0 = dsm;
    __half* sA1 = dsm + 128 * SROWA;
    __half* sB  = dsm + 2 * 128 * SROWA;

    const int tid  = threadIdx.x;
    const int warp = tid >> 5;
    const int lane = tid & 31;
    const int g    = lane >> 2;
    const int tg   = lane & 3;
    const int m0   = (int)(blockIdx.x >> 1) * 128;
    const int n0   = (int)(blockIdx.x & 1) * 128;
    const int wm   = (warp >> 2) * 64;
    const int wn   = (warp & 3) * 32;

    const int srow = tid >> 1;
    const int part = (tid & 1) * 16;     // A: 16-half slot
    const int colh = (tid & 1) * 128;    // B: 128-half slot
    const bool va  = (m0 + srow) < M;

    // ---- stage full B (K=256) once ----
    #pragma unroll
    for (int i = 0; i < 32; i++) {
        const float4 v = *(const float4*)(B + (size_t)(n0 + srow) * 256 + colh + i * 4);
        *(uint2*)&sB[srow * SROWB + colh + i * 4] =
            make_uint2(pack_h2(v.x, v.y), pack_h2(v.z, v.w));
    }
    // ---- stage A chunk 0 ----
    #pragma unroll
    for (int i = 0; i < 4; i++) {
        const float4 v = va ? *(const float4*)(A + (size_t)(m0 + srow) * 256 + part + i * 4)
                            : make_float4(0.f, 0.f, 0.f, 0.f);
        *(uint2*)&sA0[srow * SROWA + part + i * 4] =
            make_uint2(pack_h2(v.x, v.y), pack_h2(v.z, v.w));
    }
    __syncthreads();

    uint32_t accH[4][4][2];
    #pragma unroll
    for (int i = 0; i < 4; i++)
        #pragma unroll
        for (int j = 0; j < 4; j++) { accH[i][j][0] = 0u; accH[i][j][1] = 0u; }

    const uint32_t uA0 = (uint32_t)__cvta_generic_to_shared(sA0);
    const uint32_t uA1 = (uint32_t)__cvta_generic_to_shared(sA1);
    const uint32_t uB  = (uint32_t)__cvta_generic_to_shared(sB);
    const uint32_t offA = (uint32_t)(((lane & 15) * SROWA + (lane >> 4) * 8) * 2);
    const uint32_t offB = (uint32_t)((((lane >> 4) * 8 + (lane & 7)) * SROWB
                                      + ((lane >> 3) & 1) * 8) * 2);

    #pragma unroll 1
    for (int c = 0; c < 8; c++) {
        // prefetch A chunk c+1 into registers (overlaps mma)
        float4 pa[4];
        if (c < 7) {
            const int kk = (c + 1) * 32 + part;
            #pragma unroll
            for (int i = 0; i < 4; i++)
                pa[i] = va ? *(const float4*)(A + (size_t)(m0 + srow) * 256 + kk + i * 4)
                           : make_float4(0.f, 0.f, 0.f, 0.f);
        }

        const uint32_t ub = (c & 1) ? uA1 : uA0;
        #pragma unroll
        for (int ks = 0; ks < 2; ks++) {
            uint32_t af[4][4];
            #pragma unroll
            for (int mf = 0; mf < 4; mf++)
                ldmatrix_x4(af[mf], ub + offA
                            + (uint32_t)(((wm + mf * 16) * SROWA + ks * 16) * 2));
            uint32_t bf[2][4];
            #pragma unroll
            for (int p = 0; p < 2; p++)
                ldmatrix_x4(bf[p], uB + offB
                            + (uint32_t)(((wn + p * 16) * SROWB + c * 32 + ks * 16) * 2));
            #pragma unroll
            for (int mf = 0; mf < 4; mf++)
                #pragma unroll
                for (int nf = 0; nf < 4; nf++)
                    mma_f16_f16acc(accH[mf][nf], af[mf], bf[nf >> 1][(nf & 1) * 2],
                                   bf[nf >> 1][(nf & 1) * 2 + 1]);
        }

        if (c < 7) {
            __half* d = (c & 1) ? sA0 : sA1;   // buffer (c+1)&1
            #pragma unroll
            for (int i = 0; i < 4; i++)
                *(uint2*)&d[srow * SROWA + part + i * 4] =
                    make_uint2(pack_h2(pa[i].x, pa[i].y), pack_h2(pa[i].z, pa[i].w));
        }
        __syncthreads();
    }

    // ---- epilogue: bias + relu, fp16 store (row stride 256) ----
    #pragma unroll
    for (int mf = 0; mf < 4; mf++) {
        #pragma unroll
        for (int nf = 0; nf < 4; nf++) {
            const int cc = n0 + wn + nf * 8 + tg * 2;
            const float b0 = __ldg(&bias[cc]);
            const float b1 = __ldg(&bias[cc + 1]);
            #pragma unroll
            for (int half = 0; half < 2; half++) {
                const int m = m0 + wm + mf * 16 + g + half * 8;
                if (m < M) {
                    const float2 f = __half22float2(*(__half2*)&accH[mf][nf][half]);
                    const uint32_t p = pack_h2(fmaxf(f.x + b0, 0.f), fmaxf(f.y + b1, 0.f));
                    *(uint32_t*)(C + (size_t)m * 256 + cc) = p;
                }
            }
        }
    }
}

// ===========================================================================
// GEMM-C: out[m, n0..n0+127] = relu( cat[m,:] @ Ww[n,:] + Wb[n] ), fp32 out.
// A fp16 [M,512] (g_cat), B fp32 [256,512]. Same tiling as GEMM-A but both
// A and B double-buffered per chunk; fp32 accumulators (output is direct).
// ===========================================================================
template <int NCHUNK>
__global__ __launch_bounds__(256) void gemm_c_kernel(
    const __half* __restrict__ A, const float* __restrict__ B,
    const float* __restrict__ bias, float* __restrict__ C, int M)
{
    __shared__ __half sA[2][128 * SROWA];
    __shared__ __half sB[2][128 * SROWA];

    const int tid  = threadIdx.x;
    const int warp = tid >> 5;
    const int lane = tid & 31;
    const int g    = lane >> 2;
    const int tg   = lane & 3;
    const int m0   = (int)(blockIdx.x >> 1) * 128;
    const int n0   = (int)(blockIdx.x & 1) * 128;
    const int wm   = (warp >> 2) * 64;
    const int wn   = (warp & 3) * 32;
    const int K    = NCHUNK * 32;

    const int srow = tid >> 1;
    const int part = (tid & 1) * 16;
    const bool va  = (m0 + srow) < M;

    float acc[4][4][4];
    #pragma unroll
    for (int i = 0; i < 4; i++)
        #pragma unroll
        for (int j = 0; j < 4; j++)
            #pragma unroll
            for (int r = 0; r < 4; r++) acc[i][j][r] = 0.f;

    // ---- stage chunk 0 ----
    #pragma unroll
    for (int i = 0; i < 4; i++) {
        const uint2 ap = va ? *(const uint2*)(A + (size_t)(m0 + srow) * K + part + i * 4)
                            : make_uint2(0u, 0u);
        *(uint2*)&sA[0][srow * SROWA + part + i * 4] = ap;
        const float4 vb = *(const float4*)(B + (size_t)(n0 + srow) * K + part + i * 4);
        *(uint2*)&sB[0][srow * SROWA + part + i * 4] =
            make_uint2(pack_h2(vb.x, vb.y), pack_h2(vb.z, vb.w));
    }
    __syncthreads();

    const uint32_t uA0 = (uint32_t)__cvta_generic_to_shared(&sA[0][0]);
    const uint32_t uA1 = (uint32_t)__cvta_generic_to_shared(&sA[1][0]);
    const uint32_t uB0 = (uint32_t)__cvta_generic_to_shared(&sB[0][0]);
    const uint32_t uB1 = (uint32_t)__cvta_generic_to_shared(&sB[1][0]);
    const uint32_t offA = (uint32_t)(((lane & 15) * SROWA + (lane >> 4) * 8) * 2);
    const uint32_t offB = (uint32_t)((((lane >> 4) * 8 + (lane & 7)) * SROWA
                                      + ((lane >> 3) & 1) * 8) * 2);

    #pragma unroll 1
    for (int c = 0; c < NCHUNK; c++) {
        uint2  pa[4];
        float4 pb[4];
        if (c + 1 < NCHUNK) {
            const int kk = (c + 1) * 32 + part;
            #pragma unroll
            for (int i = 0; i < 4; i++) {
                pa[i] = va ? *(const uint2*)(A + (size_t)(m0 + srow) * K + kk + i * 4)
                           : make_uint2(0u, 0u);
                pb[i] = *(const float4*)(B + (size_t)(n0 + srow) * K + kk + i * 4);
            }
        }

        const uint32_t ubA = (c & 1) ? uA1 : uA0;
        const uint32_t ubB = (c & 1) ? uB1 : uB0;
        #pragma unroll
        for (int ks = 0; ks < 2; ks++) {
            uint32_t af[4][4];
            #pragma unroll
            for (int mf = 0; mf < 4; mf++)
                ldmatrix_x4(af[mf], ubA + offA
                            + (uint32_t)(((wm + mf * 16) * SROWA + ks * 16) * 2));
            uint32_t bf[2][4];
            #pragma unroll
            for (int p = 0; p < 2; p++)
                ldmatrix_x4(bf[p], ubB + offB
                            + (uint32_t)(((wn + p * 16) * SROWA + ks * 16) * 2));
            #pragma unroll
            for (int mf = 0; mf < 4; mf++)
                #pragma unroll
                for (int nf = 0; nf < 4; nf++)
                    mma_f16_f32acc(acc[mf][nf], af[mf], bf[nf >> 1][(nf & 1) * 2],
                                   bf[nf >> 1][(nf & 1) * 2 + 1]);
        }

        if (c + 1 < NCHUNK) {
            const uint32_t nb = (c + 1) & 1;
            __half* dA = nb ? &sA[1][0] : &sA[0][0];
            __half* dB = nb ? &sB[1][0] : &sB[0][0];
            #pragma unroll
            for (int i = 0; i < 4; i++) {
                *(uint2*)&dA[srow * SROWA + part + i * 4] = pa[i];
                *(uint2*)&dB[srow * SROWA + part + i * 4] =
                    make_uint2(pack_h2(pb[i].x, pb[i].y), pack_h2(pb[i].z, pb[i].w));
            }
        }
        __syncthreads();
    }

    // ---- epilogue: bias + relu, fp32 store (row stride 256) ----
    #pragma unroll
    for (int mf = 0; mf < 4; mf++) {
        #pragma unroll
        for (int half = 0; half < 2; half++) {
            const int m = m0 + wm + mf * 16 + g + half * 8;
            if (m < M) {
                #pragma unroll
                for (int nf = 0; nf < 4; nf++) {
                    const int cc = n0 + wn + nf * 8 + tg * 2;
                    const float v0 = fmaxf(acc[mf][nf][half * 2 + 0] + __ldg(&bias[cc]),     0.f);
                    const float v1 = fmaxf(acc[mf][nf][half * 2 + 1] + __ldg(&bias[cc + 1]), 0.f);
                    *(float2*)(C + (size_t)m * 256 + cc) = make_float2(v0, v1);
                }
            }
        }
    }
}

// ---------------------------------------------------------------------------
// Aggregation: h_agg[n] = sum_t w[n,t]*QH[nb[n,t]] / sum_t w[n,t]
// QH fp16 (L2-resident). One warp per node; also copies h[nodeset[n]]
// (fp32 -> fp16) into the first half of the fp16 concat row.
// ---------------------------------------------------------------------------
__global__ __launch_bounds__(256) void agg_kernel(
    const float* __restrict__ h, const int* __restrict__ nodeset,
    const int* __restrict__ nb_nodes, const float* __restrict__ nb_w)
{
    __shared__ int   s_idx[8][TN];
    __shared__ float s_w[8][TN];

    const int tid  = threadIdx.x;
    const int warp = tid >> 5;
    const int lane = tid & 31;
    const int n    = blockIdx.x * 8 + warp;   // 20000/8 = 2500 blocks exact

    for (int j = lane; j < TN; j += 32) {
        s_idx[warp][j] = nb_nodes[n * TN + j];
        s_w[warp][j]   = nb_w[n * TN + j];
    }
    __syncwarp();

    float wsum = 0.f;
    #pragma unroll
    for (int t = 0; t < TN; t++) wsum += s_w[warp][t];   // smem broadcast

    const int colb = lane * 8;
    float acc[8];
    #pragma unroll
    for (int i = 0; i < 8; i++) acc[i] = 0.f;

    #pragma unroll 10
    for (int t = 0; t < TN; t++) {
        const int   idx = s_idx[warp][t];
        const float w   = s_w[warp][t];
        union { uint4 u; __half2 h2[4]; } q;
        q.u = *(const uint4*)(g_qh + (size_t)idx * HIDF + colb);
        #pragma unroll
        for (int i = 0; i < 4; i++) {
            const float2 f = __half22float2(q.h2[i]);
            acc[2 * i]     += w * f.x;
            acc[2 * i + 1] += w * f.y;
        }
    }
    const float inv = 1.f / wsum;
    union { uint4 u; __half2 h2[4]; } o;
    #pragma unroll
    for (int i = 0; i < 4; i++)
        o.h2[i] = __float22half2_rn(make_float2(acc[2 * i] * inv, acc[2 * i + 1] * inv));
    *(uint4*)(g_cat + (size_t)n * CATF + INF + colb) = o.u;

    const int self = nodeset[n];
    const float4 s0 = *(const float4*)(h + (size_t)self * INF + colb);
    const float4 s1 = *(const float4*)(h + (size_t)self * INF + colb + 4);
    union { uint4 u; __half2 h2[4]; } sc;
    sc.h2[0] = __float22half2_rn(make_float2(s0.x, s0.y));
    sc.h2[1] = __float22half2_rn(make_float2(s0.z, s0.w));
    sc.h2[2] = __float22half2_rn(make_float2(s1.x, s1.y));
    sc.h2[3] = __float22half2_rn(make_float2(s1.z, s1.w));
    *(uint4*)(g_cat + (size_t)n * CATF + colb) = sc.u;
}

// ---------------------------------------------------------------------------
// In-place row L2 normalize of d_out [20000, 256]; one warp per row
// ---------------------------------------------------------------------------
__global__ __launch_bounds__(256) void norm_kernel(float* __restrict__ out)
{
    const int gwarp = (blockIdx.x * blockDim.x + threadIdx.x) >> 5;
    const int lane  = threadIdx.x & 31;
    if (gwarp >= NNODES) return;
    float* row = out + (size_t)gwarp * OUTF;

    float4 v0 = *(float4*)&row[lane * 4];
    float4 v1 = *(float4*)&row[128 + lane * 4];
    float ss = v0.x * v0.x + v0.y * v0.y + v0.z * v0.z + v0.w * v0.w
             + v1.x * v1.x + v1.y * v1.y + v1.z * v1.z + v1.w * v1.w;
    #pragma unroll
    for (int o = 16; o; o >>= 1) ss += __shfl_xor_sync(0xffffffffu, ss, o);
    const float inv = rsqrtf(ss);
    v0.x *= inv; v0.y *= inv; v0.z *= inv; v0.w *= inv;
    v1.x *= inv; v1.y *= inv; v1.z *= inv; v1.w *= inv;
    *(float4*)&row[lane * 4]       = v0;
    *(float4*)&row[128 + lane * 4] = v1;
}

// ---------------------------------------------------------------------------
extern "C" void kernel_launch(void* const* d_in, const int* in_sizes, int n_in,
                              void* d_out, int out_size)
{
    const float* h        = (const float*)d_in[0];
    const int*   nodeset  = (const int*)d_in[1];
    const int*   nb_nodes = (const int*)d_in[2];
    const float* nb_w     = (const float*)d_in[3];
    const float* Qw       = (const float*)d_in[4];
    const float* Qb       = (const float*)d_in[5];
    const float* Ww       = (const float*)d_in[6];
    const float* Wb       = (const float*)d_in[7];
    float*       out      = (float*)d_out;

    __half* qh  = nullptr;
    __half* cat = nullptr;
    cudaGetSymbolAddress((void**)&qh,  g_qh);
    cudaGetSymbolAddress((void**)&cat, g_cat);

    static bool attr_done = false;
    if (!attr_done) {
        cudaFuncSetAttribute(gemm_a_kernel,
                             cudaFuncAttributeMaxDynamicSharedMemorySize, GEMM_A_SMEM);
        attr_done = true;
    }

    // 1) QH = relu(h @ Qw^T + Qb) -> fp16 [100000, 256]
    {
        const int tilesM = (NODES_TOTAL + 127) / 128;   // 782
        gemm_a_kernel<<<tilesM * 2, 256, GEMM_A_SMEM>>>(h, Qw, Qb, qh, NODES_TOTAL);
    }
    // 2) aggregate + self gather -> g_cat fp16 [20000, 512]
    agg_kernel<<<NNODES / 8, 256>>>(h, nodeset, nb_nodes, nb_w);

    // 3) out = relu(g_cat @ Ww^T + Wb)  [20000, 256], K=512 (16 chunks)
    {
        const int tilesM = (NNODES + 127) / 128;        // 157
        gemm_c_kernel<16><<<tilesM * 2, 256>>>(cat, Ww, Wb, out, NNODES);
    }
    // 4) in-place L2 normalize
    norm_kernel<<<(NNODES * 32 + 255) / 256, 256>>>(out);
}